// round 17
// baseline (speedup 1.0000x reference)
#include <cuda_runtime.h>
#include <cuda_fp16.h>
#include <cstdint>
#include <math.h>

#define N_    8
#define C_    256
#define H_    64
#define W_    64
#define K_    9
#define P_    4096          // 64*64
#define CK_   2304          // C_*K_
#define COUT_ 256
#define NCHUNK 24           // CK_/96

// ------------------------------- scratch ------------------------------------
__device__ __half g_xh[(size_t)N_ * P_ * C_];     // x NHWC fp16
__device__ __half g_ch[(size_t)N_ * P_ * CK_];    // cols, K-major [n][p][k*256+c]
__device__ __half g_wh[COUT_ * CK_];              // weights [cout][k*256+c]

// ---------------- small PTX helpers (family-agnostic only) ------------------
__device__ __forceinline__ uint32_t smem_to_u32(const void* p) {
    uint32_t a;
    asm("{ .reg .u64 t; cvta.to.shared.u64 t, %1; cvt.u32.u64 %0, t; }"
        : "=r"(a) : "l"(p));
    return a;
}
__device__ __forceinline__ void cp16(uint32_t dst, const void* src) {
    asm volatile("cp.async.cg.shared.global [%0], [%1], 16;"
                 :: "r"(dst), "l"(src));
}
__device__ __forceinline__ void cp_commit() {
    asm volatile("cp.async.commit_group;" ::: "memory");
}
template <int NN>
__device__ __forceinline__ void cp_wait() {
    asm volatile("cp.async.wait_group %0;" :: "n"(NN) : "memory");
}
__device__ __forceinline__ void ldsm4(uint32_t* r, uint32_t addr) {
    asm volatile("ldmatrix.sync.aligned.m8n8.x4.shared.b16 {%0,%1,%2,%3}, [%4];"
        : "=r"(r[0]), "=r"(r[1]), "=r"(r[2]), "=r"(r[3]) : "r"(addr));
}
__device__ __forceinline__ void mma16816h(float* d, const uint32_t* a,
                                          uint32_t b0, uint32_t b1) {
    asm volatile("mma.sync.aligned.m16n8k16.row.col.f32.f16.f16.f32 "
        "{%0,%1,%2,%3}, {%4,%5,%6,%7}, {%8,%9}, {%0,%1,%2,%3};"
        : "+f"(d[0]), "+f"(d[1]), "+f"(d[2]), "+f"(d[3])
        : "r"(a[0]), "r"(a[1]), "r"(a[2]), "r"(a[3]), "r"(b0), "r"(b1));
}

// ---------------------------------------------------------------------------
// Kernel P: fused prep. Blocks [0, 4096): x NCHW fp32 -> NHWC fp16 transpose
// (float4 global loads). Blocks [4096, 6400): weight convert + reorder.
// ---------------------------------------------------------------------------
__global__ __launch_bounds__(256)
void prep_k(const float* __restrict__ x, const float* __restrict__ w) {
    const int bid = blockIdx.x;
    if (bid < 4096) {                    // ---- nhwc transpose ----
        __shared__ float sm[64][33];
        const int s0 = (bid & 127) * 32;
        const int c0 = ((bid >> 7) & 3) * 64;
        const int n  = bid >> 9;
        const int tid = threadIdx.x;

        // load: 64 ch x 8 float4 = 512 vec loads, 2 per thread
        #pragma unroll
        for (int i = 0; i < 2; ++i) {
            int idx = tid + i * 256;         // 0..511
            int ch  = idx >> 3;
            int v   = idx & 7;
            float4 f = *(const float4*)(x
                + ((size_t)n * C_ + c0 + ch) * P_ + s0 + v * 4);
            sm[ch][v * 4 + 0] = f.x;
            sm[ch][v * 4 + 1] = f.y;
            sm[ch][v * 4 + 2] = f.z;
            sm[ch][v * 4 + 3] = f.w;
        }
        __syncthreads();

        const int tx = tid & 31;
        const int ty = tid >> 5;
        #pragma unroll
        for (int i = 0; i < 4; ++i) {
            int s = i * 8 + ty;
            __half2 h = __floats2half2_rn(sm[2 * tx][s], sm[2 * tx + 1][s]);
            *(__half2*)(g_xh + ((size_t)(n * P_ + s0 + s)) * C_ + c0 + 2 * tx) = h;
        }
    } else {                             // ---- weight convert + reorder ----
        int o = (bid - 4096) * 256 + threadIdx.x;
        if (o >= COUT_ * CK_) return;
        int cout = o / CK_;
        int r    = o % CK_;
        int k    = r >> 8;
        int c    = r & 255;
        g_wh[o] = __float2half_rn(w[(size_t)cout * CK_ + c * 9 + k]);
    }
}

// ---------------------------------------------------------------------------
// Kernel 1: deformable im2col (batched, MLP-8; HFMA2 bilinear combine).
// ---------------------------------------------------------------------------
struct Corners {
    __half2 W00, W01, W10, W11;
    const __half *c00, *c01, *c10, *c11;
};

__device__ __forceinline__ Corners corner_params(
    const float* __restrict__ ob, const __half* __restrict__ xb,
    int ky, int kx, int p)
{
    const int ho = p >> 6, wo = p & 63;
    float py = (float)(ho - 1 + ky) + __ldg(ob + p);
    float px = (float)(wo - 1 + kx) + __ldg(ob + P_ + p);

    float y0f = floorf(py), x0f = floorf(px);
    float ly = py - y0f, lx = px - x0f;
    float hy = 1.0f - ly, hx = 1.0f - lx;
    int y0 = (int)y0f, x0 = (int)x0f;
    int y1 = y0 + 1,   x1 = x0 + 1;

    bool vy0 = ((unsigned)y0 < (unsigned)H_);
    bool vy1 = ((unsigned)y1 < (unsigned)H_);
    bool vx0 = ((unsigned)x0 < (unsigned)W_);
    bool vx1 = ((unsigned)x1 < (unsigned)W_);

    int cy0 = min(max(y0, 0), H_ - 1);
    int cy1 = min(max(y1, 0), H_ - 1);
    int cx0 = min(max(x0, 0), W_ - 1);
    int cx1 = min(max(x1, 0), W_ - 1);

    Corners cp;
    cp.W00 = __float2half2_rn((vy0 && vx0) ? hy * hx : 0.0f);
    cp.W01 = __float2half2_rn((vy0 && vx1) ? hy * lx : 0.0f);
    cp.W10 = __float2half2_rn((vy1 && vx0) ? ly * hx : 0.0f);
    cp.W11 = __float2half2_rn((vy1 && vx1) ? ly * lx : 0.0f);
    cp.c00 = xb + (size_t)(cy0 * W_ + cx0) * C_;
    cp.c01 = xb + (size_t)(cy0 * W_ + cx1) * C_;
    cp.c10 = xb + (size_t)(cy1 * W_ + cx0) * C_;
    cp.c11 = xb + (size_t)(cy1 * W_ + cx1) * C_;
    return cp;
}

__device__ __forceinline__ uint4 bilin_combine(const Corners& cp,
        uint4 a00, uint4 a01, uint4 a10, uint4 a11)
{
    union { __half2 h[4]; uint4 v; } o;
    const __half2* h00 = (const __half2*)&a00;
    const __half2* h01 = (const __half2*)&a01;
    const __half2* h10 = (const __half2*)&a10;
    const __half2* h11 = (const __half2*)&a11;
    #pragma unroll
    for (int j = 0; j < 4; ++j) {
        __half2 r = __hmul2(cp.W00, h00[j]);
        r = __hfma2(cp.W01, h01[j], r);
        r = __hfma2(cp.W10, h10[j], r);
        r = __hfma2(cp.W11, h11[j], r);
        o.h[j] = r;
    }
    return o.v;
}

__global__ __launch_bounds__(256)
void im2col_k(const float* __restrict__ off)
{
    const int lane = threadIdx.x & 31;
    const int wib  = threadIdx.x >> 5;        // 0..7
    const int bid  = blockIdx.x;              // N*K*P/16 = 18432 blocks
    const int p0   = (bid & 255) * 16;
    const int k    = (bid >> 8) % 9;
    const int n    = bid / (256 * 9);
    const int ky   = k / 3, kx = k % 3;

    const int pA = p0 + wib;
    const int pB = p0 + 8 + wib;

    const float* ob = off + ((size_t)n * (2 * K_) + k * 2) * P_;
    const __half* xb = g_xh + ((size_t)n << 20);   // n * P_ * C_

    Corners ca = corner_params(ob, xb, ky, kx, pA);
    Corners cb = corner_params(ob, xb, ky, kx, pB);

    uint4 a00 = __ldg((const uint4*)ca.c00 + lane);
    uint4 a01 = __ldg((const uint4*)ca.c01 + lane);
    uint4 a10 = __ldg((const uint4*)ca.c10 + lane);
    uint4 a11 = __ldg((const uint4*)ca.c11 + lane);
    uint4 b00 = __ldg((const uint4*)cb.c00 + lane);
    uint4 b01 = __ldg((const uint4*)cb.c01 + lane);
    uint4 b10 = __ldg((const uint4*)cb.c10 + lane);
    uint4 b11 = __ldg((const uint4*)cb.c11 + lane);

    uint4 ra = bilin_combine(ca, a00, a01, a10, a11);
    uint4 rb = bilin_combine(cb, b00, b01, b10, b11);

    *(uint4*)(g_ch + ((size_t)(n * P_ + pA)) * CK_ + k * 256 + lane * 8) = ra;
    *(uint4*)(g_ch + ((size_t)(n * P_ + pB)) * CK_ + k * 256 + lane * 8) = rb;
}

// ---------------------------------------------------------------------------
// Kernel 2: fp16 mma.sync GEMM.
// CTA tile 128 cout x 128 pixels, 8 warps of 64x32.
// K-chunk 96, 2-stage cp.async ring, one barrier per chunk.
// 104 KB smem, 2 CTAs/SM.
// ---------------------------------------------------------------------------
#define PITCH     208           // 192B data + 16B pad: r*52 mod 32 covers all
                                // 32 banks over 8 rows -> conflict-free ldmatrix
#define A_OFF     0
#define B_OFF     (128 * PITCH)             // 26624
#define STAGE     (2 * 128 * PITCH)         // 53248
#define NSTAGE    2
#define SMEM_TOTAL (NSTAGE * STAGE)         // 106496 B

__device__ __forceinline__ void load_stage(uint32_t st, int chunk,
                                           int cout0, int n, int p0, int tid)
{
    const size_t cb = (size_t)chunk * 192;       // byte offset in 4608 B row
    #pragma unroll
    for (int i = 0; i < 12; ++i) {
        int idx = tid + i * 256;                 // 0..3071
        if (idx < 1536) {                        // A: weights, 128 rows x 12 vec
            int row = idx / 12;
            int c16 = (idx % 12) * 16;
            cp16(st + A_OFF + row * PITCH + c16,
                 (const char*)g_wh + (size_t)(cout0 + row) * (CK_ * 2) + cb + c16);
        } else {                                 // B: cols, 128 rows x 12 vec
            int r   = idx - 1536;
            int row = r / 12;
            int c16 = (r % 12) * 16;
            cp16(st + B_OFF + row * PITCH + c16,
                 (const char*)g_ch + ((size_t)(n * P_ + p0 + row)) * (CK_ * 2) + cb + c16);
        }
    }
}

__global__ __launch_bounds__(256, 2)
void gemm_k(const float* __restrict__ bias, float* __restrict__ out)
{
    extern __shared__ __align__(128) char smem[];
    const uint32_t sb = smem_to_u32(smem);

    const int tid    = threadIdx.x;
    const int lane   = tid & 31;
    const int wid    = tid >> 5;
    const int warp_m = wid & 1;       // 64-cout half
    const int warp_n = wid >> 1;      // 32-pixel quarter

    const int cout0 = blockIdx.x * 128;
    const int p0    = blockIdx.y * 128;
    const int n     = blockIdx.z;

    float d[4][4][4];
    #pragma unroll
    for (int mi = 0; mi < 4; ++mi)
        #pragma unroll
        for (int ni = 0; ni < 4; ++ni)
            #pragma unroll
            for (int j = 0; j < 4; ++j) d[mi][ni][j] = 0.0f;

    load_stage(sb, 0, cout0, n, p0, tid);
    cp_commit();

    const int a_row = (lane & 15);
    const int a_c16 = (lane >> 4) << 4;
    const int b_row = (lane & 7) + ((lane >> 4) << 3);
    const int b_c16 = ((lane >> 3) & 1) << 4;

    for (int c = 0; c < NCHUNK; ++c) {
        cp_wait<0>();        // chunk c resident
        __syncthreads();     // readers of buffer (c+1)&1 (from iter c-1) done

        if (c + 1 < NCHUNK) {
            load_stage(sb + ((c + 1) & 1) * STAGE, c + 1, cout0, n, p0, tid);
            cp_commit();
        }

        const uint32_t st = sb + (c & 1) * STAGE;

        #pragma unroll
        for (int s = 0; s < 6; ++s) {           // six k16 steps per chunk
            uint32_t ah[4][4];
            #pragma unroll
            for (int mi = 0; mi < 4; ++mi)
                ldsm4(ah[mi], st + A_OFF
                      + (warp_m * 64 + mi * 16 + a_row) * PITCH + s * 32 + a_c16);
            uint32_t bhf[2][4];
            #pragma unroll
            for (int np = 0; np < 2; ++np)
                ldsm4(bhf[np], st + B_OFF
                      + (warp_n * 32 + np * 16 + b_row) * PITCH + s * 32 + b_c16);
            #pragma unroll
            for (int mi = 0; mi < 4; ++mi)
                #pragma unroll
                for (int ni = 0; ni < 4; ++ni) {
                    const int np = ni >> 1, sub = (ni & 1) * 2;
                    mma16816h(d[mi][ni], ah[mi], bhf[np][sub], bhf[np][sub + 1]);
                }
        }
    }

    // epilogue: D fragment (row=cout, col=pixel) -> out[n][cout][p] + bias
    const int gr = lane >> 2;
    const int gc = (lane & 3) * 2;
    #pragma unroll
    for (int mi = 0; mi < 4; ++mi) {
        const int cout = cout0 + warp_m * 64 + mi * 16 + gr;
        const float bv0 = __ldg(bias + cout);
        const float bv1 = __ldg(bias + cout + 8);
        float* base = out + ((size_t)n * COUT_ + cout) * P_;
        #pragma unroll
        for (int ni = 0; ni < 4; ++ni) {
            const int px = p0 + warp_n * 32 + ni * 8 + gc;
            float2 v0 = make_float2(d[mi][ni][0] + bv0, d[mi][ni][1] + bv0);
            float2 v1 = make_float2(d[mi][ni][2] + bv1, d[mi][ni][3] + bv1);
            *(float2*)(base + px)          = v0;
            *(float2*)(base + 8 * P_ + px) = v1;
        }
    }
}

// ---------------------------------------------------------------------------
extern "C" void kernel_launch(void* const* d_in, const int* in_sizes, int n_in,
                              void* d_out, int out_size)
{
    const float* x    = (const float*)d_in[0];
    const float* off  = (const float*)d_in[1];
    const float* wgt  = (const float*)d_in[2];
    const float* bias = (const float*)d_in[3];
    float* out = (float*)d_out;

    static bool attr_set = false;
    if (!attr_set) {
        cudaFuncSetAttribute(gemm_k, cudaFuncAttributeMaxDynamicSharedMemorySize,
                             SMEM_TOTAL);
        attr_set = true;
    }

    prep_k<<<4096 + (COUT_ * CK_ + 255) / 256, 256>>>(x, wgt);
    im2col_k<<<N_ * K_ * P_ / 16, 256>>>(off);

    dim3 grid(COUT_ / 128, P_ / 128, N_);   // (2, 32, 8) = 512 CTAs
    gemm_k<<<grid, 256, SMEM_TOTAL>>>(bias, out);
}